// round 2
// baseline (speedup 1.0000x reference)
#include <cuda_runtime.h>

#define B_ 8
#define C_ 64
#define H_ 256
#define W_ 256
#define HW_ (H_ * W_)

// Each thread computes 4 consecutive w-pixels (float4 granularity).
// blockDim = (64, 2): 64 threads * 4 px = 256 = full row; 2 rows per block.
// Warp covers 128 contiguous pixels of one row -> h uniform per warp, so
// border branches are warp-uniform.
__global__ __launch_bounds__(128, 8)
void conv_attn_v4(const float* __restrict__ q,
                  const float* __restrict__ k,
                  const float* __restrict__ v,
                  float* __restrict__ out)
{
    const int w0 = threadIdx.x * 4;            // 0..252
    const int h  = blockIdx.y * 2 + threadIdx.y;
    const int b  = blockIdx.z;

    const long cb = (long)b * C_ * HW_;        // batch base
    const int  rowoff = h * W_ + w0;

    const bool has_left  = (w0 > 0);
    const bool has_right = (w0 + 4 < W_);

    // scores: s[px][tap]
    float s[4][9];
#pragma unroll
    for (int j = 0; j < 4; j++)
#pragma unroll
        for (int i = 0; i < 9; i++) s[j][i] = 0.0f;

    // ---------------- Pass 1: q . shifted(k) ----------------
#pragma unroll 2
    for (int c = 0; c < C_; c++) {
        const float* qc = q + cb + (long)c * HW_;
        const float* kc = k + cb + (long)c * HW_;

        const float4 qv = *reinterpret_cast<const float4*>(qc + rowoff);
        const float qa[4] = {qv.x, qv.y, qv.z, qv.w};

#pragma unroll
        for (int dy = 0; dy < 3; dy++) {
            const int hh = h + dy - 1;
            if (hh < 0 || hh >= H_) continue;   // warp-uniform
            const float* row = kc + hh * W_ + w0;

            float a[6];
            a[0] = has_left  ? row[-1] : 0.0f;
            const float4 m = *reinterpret_cast<const float4*>(row);
            a[1] = m.x; a[2] = m.y; a[3] = m.z; a[4] = m.w;
            a[5] = has_right ? row[4] : 0.0f;

#pragma unroll
            for (int j = 0; j < 4; j++) {
#pragma unroll
                for (int dx = 0; dx < 3; dx++) {
                    s[j][dy * 3 + dx] = fmaf(qa[j], a[j + dx], s[j][dy * 3 + dx]);
                }
            }
        }
    }

    // ---------------- Softmax over 9 taps, per pixel ----------------
    // OOB taps carry score 0 (zero-padding in reference) — already satisfied.
#pragma unroll
    for (int j = 0; j < 4; j++) {
        float m = s[j][0];
#pragma unroll
        for (int i = 1; i < 9; i++) m = fmaxf(m, s[j][i]);
        float sum = 0.0f;
#pragma unroll
        for (int i = 0; i < 9; i++) { s[j][i] = __expf(s[j][i] - m); sum += s[j][i]; }
        const float inv = 1.0f / sum;
#pragma unroll
        for (int i = 0; i < 9; i++) s[j][i] *= inv;
    }

    // ---------------- Pass 2: out = sum_i w_i * shifted(v) ----------------
#pragma unroll 2
    for (int c = 0; c < C_; c++) {
        const float* vc = v + cb + (long)c * HW_;

        float acc[4] = {0.0f, 0.0f, 0.0f, 0.0f};

#pragma unroll
        for (int dy = 0; dy < 3; dy++) {
            const int hh = h + dy - 1;
            if (hh < 0 || hh >= H_) continue;
            const float* row = vc + hh * W_ + w0;

            float a[6];
            a[0] = has_left  ? row[-1] : 0.0f;
            const float4 m = *reinterpret_cast<const float4*>(row);
            a[1] = m.x; a[2] = m.y; a[3] = m.z; a[4] = m.w;
            a[5] = has_right ? row[4] : 0.0f;

#pragma unroll
            for (int j = 0; j < 4; j++) {
#pragma unroll
                for (int dx = 0; dx < 3; dx++) {
                    acc[j] = fmaf(s[j][dy * 3 + dx], a[j + dx], acc[j]);
                }
            }
        }

        float4 o;
        o.x = acc[0]; o.y = acc[1]; o.z = acc[2]; o.w = acc[3];
        *reinterpret_cast<float4*>(out + cb + (long)c * HW_ + rowoff) = o;
    }
}

extern "C" void kernel_launch(void* const* d_in, const int* in_sizes, int n_in,
                              void* d_out, int out_size)
{
    const float* q = (const float*)d_in[0];
    const float* k = (const float*)d_in[1];
    const float* v = (const float*)d_in[2];
    float* out = (float*)d_out;

    dim3 block(64, 2);          // 128 threads: full 256-px row x 2 rows
    dim3 grid(1, H_ / 2, B_);   // 1024 blocks
    conv_attn_v4<<<grid, block>>>(q, k, v, out);
}